// round 1
// baseline (speedup 1.0000x reference)
#include <cuda_runtime.h>
#include <cuda_bf16.h>

// CenterLoss: loss = (1/B) * sum_i [ ||x_i||^2/m_i^2 + ||c_{l_i}||^2 - 2*(x_i . c_{l_i})/m_i ]
//   with m_i = max(||x_i||, 1e-12)
// B = 16384, C = 8192, D = 64. Only the labeled column of the distmat survives
// the mask, so no GEMM is needed — just a gather + per-row dots.

#define FEAT 64
#define EPS 1e-12f

// Flag: 1 if labels buffer is int64 (odd 32-bit words all zero), 0 if int32.
__device__ int g_labels_is_i64;

__global__ void detect_labels_kernel(const unsigned int* __restrict__ labels_raw)
{
    // One warp. Inspect odd 32-bit words of the first 128 "int64 slots".
    // int64 labels in [0, 8192) -> high words are 0. Random int32 labels ->
    // essentially impossible for 128 consecutive values to all be zero.
    unsigned int acc = 0;
    #pragma unroll
    for (int i = 0; i < 4; ++i) {
        int idx = 2 * (threadIdx.x + 32 * i) + 1;  // odd words 1,3,...,255
        acc |= labels_raw[idx];
    }
    #pragma unroll
    for (int o = 16; o; o >>= 1)
        acc |= __shfl_xor_sync(0xffffffffu, acc, o);
    if (threadIdx.x == 0)
        g_labels_is_i64 = (acc == 0u) ? 1 : 0;
}

__global__ void __launch_bounds__(256)
center_loss_kernel(const float* __restrict__ x,
                   const void* __restrict__ labels,
                   const float* __restrict__ centers,
                   float* __restrict__ out,
                   int batch, float inv_batch)
{
    const int lane = threadIdx.x & 31;
    const int warp_in_blk = threadIdx.x >> 5;
    const int gwarp = (blockIdx.x * blockDim.x + threadIdx.x) >> 5;
    const int nwarps = (gridDim.x * blockDim.x) >> 5;
    const int is_i64 = g_labels_is_i64;

    float local = 0.0f;

    for (int row = gwarp; row < batch; row += nwarps) {
        long long lab;
        if (is_i64) lab = ((const long long*)labels)[row];
        else        lab = (long long)((const int*)labels)[row];

        const float2* xr = (const float2*)(x + (size_t)row * FEAT);
        const float2* cr = (const float2*)(centers + (size_t)lab * FEAT);
        float2 xv = xr[lane];
        float2 cv = cr[lane];

        float sxx = xv.x * xv.x + xv.y * xv.y;
        float sxc = xv.x * cv.x + xv.y * cv.y;
        float scc = cv.x * cv.x + cv.y * cv.y;

        #pragma unroll
        for (int o = 16; o; o >>= 1) {
            sxx += __shfl_xor_sync(0xffffffffu, sxx, o);
            sxc += __shfl_xor_sync(0xffffffffu, sxc, o);
            scc += __shfl_xor_sync(0xffffffffu, scc, o);
        }

        if (lane == 0) {
            float m = fmaxf(sqrtf(sxx), EPS);
            float dist = sxx / (m * m) + scc - 2.0f * sxc / m;
            local += dist;
        }
    }

    // Block reduction of per-warp partials (valid only on lane 0 of each warp)
    __shared__ float ssum[8];
    if (lane == 0) ssum[warp_in_blk] = local;
    __syncthreads();
    if (threadIdx.x == 0) {
        float s = 0.0f;
        int nw = blockDim.x >> 5;
        #pragma unroll
        for (int i = 0; i < 8; ++i)
            if (i < nw) s += ssum[i];
        atomicAdd(out, s * inv_batch);
    }
}

extern "C" void kernel_launch(void* const* d_in, const int* in_sizes, int n_in,
                              void* d_out, int out_size)
{
    const float* x       = (const float*)d_in[0];
    const void*  labels  = d_in[1];
    const float* centers = (const float*)d_in[2];
    float*       out     = (float*)d_out;

    const int batch = in_sizes[0] / FEAT;   // 16384

    // Zero the scalar output (capturable memset node).
    cudaMemsetAsync(out, 0, sizeof(float));

    detect_labels_kernel<<<1, 32>>>((const unsigned int*)labels);

    const int threads = 256;                 // 8 warps/block, warp-per-row
    const int blocks  = (batch * 32 + threads - 1) / threads;  // 2048
    center_loss_kernel<<<blocks, threads>>>(x, labels, centers, out,
                                            batch, 1.0f / (float)batch);
}

// round 2
// speedup vs baseline: 1.2566x; 1.2566x over previous
#include <cuda_runtime.h>

// CenterLoss: loss = (1/B) * sum_i [ sxx/m^2 + scc - 2*sxc/m ],  m = max(sqrt(sxx),1e-12)
// B=16384, C=8192, D=64. Single fused kernel:
//  - per-block redundant int64/int32 label detection (1KB, L2-hot)
//  - half-warp (16 lanes x float4) per row -> 2 rows/warp, 4 shuffle rounds
//  - device-scratch accumulator + last-block finalize (no memset, no 2nd launch)

#define EPS 1e-12f

__device__ float g_acc;            // zero-init at load; reset by finalizer each run
__device__ unsigned int g_count;   // ditto

__global__ void __launch_bounds__(256)
center_loss_kernel(const float4* __restrict__ x,
                   const void* __restrict__ labels,
                   const float4* __restrict__ centers,
                   float* __restrict__ out,
                   float inv_batch)
{
    __shared__ int s_is64;
    __shared__ float ssum[8];

    const int tid  = threadIdx.x;
    const int lane = tid & 31;
    const int wid  = tid >> 5;

    // ---- labels dtype detection (per-block, warp 0) ----
    // int64 labels in [0,8192): odd 32-bit words of first 128 slots are all 0.
    // 128 random int32 labels all being 0 has probability ~(1/8192)^128 ~ 0.
    if (wid == 0) {
        const unsigned int* lr = (const unsigned int*)labels;
        unsigned int acc = 0;
        #pragma unroll
        for (int i = 0; i < 4; ++i)
            acc |= lr[2 * (lane + 32 * i) + 1];
        #pragma unroll
        for (int o = 16; o; o >>= 1)
            acc |= __shfl_xor_sync(0xffffffffu, acc, o);
        if (lane == 0) s_is64 = (acc == 0u) ? 1 : 0;
    }
    __syncthreads();
    const int is64 = s_is64;

    // ---- 2 rows per warp: lanes [0..15] -> row0, [16..31] -> row1 ----
    const int gw  = blockIdx.x * 8 + wid;       // global warp id
    const int row = gw * 2 + (lane >> 4);
    const int sub = lane & 15;

    const int lab = is64 ? (int)((const long long*)labels)[row]
                         : ((const int*)labels)[row];

    const float4 xv = x[row * 16 + sub];        // contiguous 256B per half-warp
    const float4 cv = centers[lab * 16 + sub];  // gathered 256B row (L2-resident)

    float sxx = xv.x*xv.x + xv.y*xv.y + xv.z*xv.z + xv.w*xv.w;
    float sxc = xv.x*cv.x + xv.y*cv.y + xv.z*cv.z + xv.w*cv.w;
    float scc = cv.x*cv.x + cv.y*cv.y + cv.z*cv.z + cv.w*cv.w;

    #pragma unroll
    for (int o = 8; o; o >>= 1) {               // reduce within each 16-lane half
        sxx += __shfl_xor_sync(0xffffffffu, sxx, o);
        sxc += __shfl_xor_sync(0xffffffffu, sxc, o);
        scc += __shfl_xor_sync(0xffffffffu, scc, o);
    }

    float local = 0.0f;
    if (sub == 0) {
        float m = fmaxf(sqrtf(sxx), EPS);
        float r = 1.0f / m;
        local = sxx * r * r + scc - 2.0f * sxc * r;
    }
    // fold lane 16's row into lane 0
    local += __shfl_xor_sync(0xffffffffu, local, 16);

    if (lane == 0) ssum[wid] = local;
    __syncthreads();

    if (tid == 0) {
        float s = 0.0f;
        #pragma unroll
        for (int i = 0; i < 8; ++i) s += ssum[i];
        atomicAdd(&g_acc, s);
        __threadfence();
        unsigned int old = atomicAdd(&g_count, 1u);
        if (old == gridDim.x - 1u) {
            // last block: read+reset scratch atomically, publish result
            float total = atomicExch(&g_acc, 0.0f);
            *out = total * inv_batch;
            g_count = 0u;
        }
    }
}

extern "C" void kernel_launch(void* const* d_in, const int* in_sizes, int n_in,
                              void* d_out, int out_size)
{
    const float4* x       = (const float4*)d_in[0];
    const void*   labels  = d_in[1];
    const float4* centers = (const float4*)d_in[2];
    float*        out     = (float*)d_out;

    const int batch = in_sizes[0] / 64;          // 16384
    const int blocks = batch / 16;               // 2 rows/warp * 8 warps = 16 rows/block
    center_loss_kernel<<<blocks, 256>>>(x, labels, centers, out,
                                        1.0f / (float)batch);
}

// round 3
// speedup vs baseline: 1.4254x; 1.1343x over previous
#include <cuda_runtime.h>

// CenterLoss: loss = (1/B) * sum_i [ sxx/m^2 + scc - 2*sxc/m ],  m = max(sqrt(sxx),1e-12)
// B=16384, C=8192, D=64.
// Latency-bound fix: 4 rows per half-warp with front-batched independent loads
// (4 labels -> 4 x.float4 -> 4 centers.float4 = 12 LDGs in flight per thread).

#define EPS 1e-12f
#define R 4   // rows per half-warp

__device__ float g_acc;            // zero at load; reset by finalizer each run
__device__ unsigned int g_count;

__global__ void __launch_bounds__(128)
center_loss_kernel(const float4* __restrict__ x,
                   const void* __restrict__ labels,
                   const float4* __restrict__ centers,
                   float* __restrict__ out,
                   float inv_batch)
{
    __shared__ int s_is64;
    __shared__ float ssum[4];

    const int tid  = threadIdx.x;
    const int lane = tid & 31;
    const int wid  = tid >> 5;

    // ---- labels dtype detection (per-block, warp 0) ----
    // int64 labels in [0,8192): odd 32-bit words of first 128 slots are all 0.
    if (wid == 0) {
        const unsigned int* lr = (const unsigned int*)labels;
        unsigned int acc = 0;
        #pragma unroll
        for (int i = 0; i < 4; ++i)
            acc |= lr[2 * (lane + 32 * i) + 1];
        #pragma unroll
        for (int o = 16; o; o >>= 1)
            acc |= __shfl_xor_sync(0xffffffffu, acc, o);
        if (lane == 0) s_is64 = (acc == 0u) ? 1 : 0;
    }
    __syncthreads();
    const int is64 = s_is64;

    const int hw   = lane >> 4;        // half-warp id (0/1)
    const int sub  = lane & 15;        // lane within half-warp
    // each half-warp handles R consecutive rows
    const int base = (((blockIdx.x * 4 + wid) * 2) + hw) * R;

    // ---- front-batched loads: labels first, then x, then centers ----
    int lab[R];
    #pragma unroll
    for (int i = 0; i < R; ++i)
        lab[i] = is64 ? (int)((const long long*)labels)[base + i]
                      : ((const int*)labels)[base + i];

    float4 xv[R];
    #pragma unroll
    for (int i = 0; i < R; ++i)
        xv[i] = x[(base + i) * 16 + sub];     // half-warp: 1KB contiguous

    float4 cv[R];
    #pragma unroll
    for (int i = 0; i < R; ++i)
        cv[i] = centers[lab[i] * 16 + sub];   // gathered 256B rows, L2-resident

    // ---- per-row sums + half-warp reduction ----
    float local = 0.0f;
    #pragma unroll
    for (int i = 0; i < R; ++i) {
        float sxx = xv[i].x*xv[i].x + xv[i].y*xv[i].y + xv[i].z*xv[i].z + xv[i].w*xv[i].w;
        float sxc = xv[i].x*cv[i].x + xv[i].y*cv[i].y + xv[i].z*cv[i].z + xv[i].w*cv[i].w;
        float scc = cv[i].x*cv[i].x + cv[i].y*cv[i].y + cv[i].z*cv[i].z + cv[i].w*cv[i].w;
        #pragma unroll
        for (int o = 8; o; o >>= 1) {
            sxx += __shfl_xor_sync(0xffffffffu, sxx, o);
            sxc += __shfl_xor_sync(0xffffffffu, sxc, o);
            scc += __shfl_xor_sync(0xffffffffu, scc, o);
        }
        if (sub == 0) {
            float m = fmaxf(sqrtf(sxx), EPS);
            float r = 1.0f / m;
            local += sxx * r * r + scc - 2.0f * sxc * r;
        }
    }

    // fold the two half-warps, then block-reduce
    local += __shfl_xor_sync(0xffffffffu, local, 16);
    if (lane == 0) ssum[wid] = local;
    __syncthreads();

    if (tid == 0) {
        float s = ssum[0] + ssum[1] + ssum[2] + ssum[3];
        atomicAdd(&g_acc, s);
        __threadfence();
        unsigned int old = atomicAdd(&g_count, 1u);
        if (old == gridDim.x - 1u) {
            float total = atomicExch(&g_acc, 0.0f);
            *out = total * inv_batch;
            g_count = 0u;
        }
    }
}

extern "C" void kernel_launch(void* const* d_in, const int* in_sizes, int n_in,
                              void* d_out, int out_size)
{
    const float4* x       = (const float4*)d_in[0];
    const void*   labels  = d_in[1];
    const float4* centers = (const float4*)d_in[2];
    float*        out     = (float*)d_out;

    const int batch  = in_sizes[0] / 64;        // 16384
    const int rows_per_block = 4 /*warps*/ * 2 /*halves*/ * R;  // 32
    const int blocks = batch / rows_per_block;  // 512
    center_loss_kernel<<<blocks, 128>>>(x, labels, centers, out,
                                        1.0f / (float)batch);
}